// round 11
// baseline (speedup 1.0000x reference)
#include <cuda_runtime.h>
#include <math_constants.h>

#define B_CONST 4096
#define D_CONST 256
#define N_CONST 8192
#define GRID    1024
#define TPB     256      // 8 warps: w<4 -> a-rows, w>=4 -> matching b-rows

// scratch (device globals — allocation forbidden; zero-initialized at load)
__device__ int g_ep[GRID];   // per-block launch counter
__device__ int g_zflag = 0;  // epoch stamp: "output zeroed by block 0"

__device__ __forceinline__ float pick4(float4 v, int s) {
    float r = v.x;
    if (s == 1) r = v.y;
    if (s == 2) r = v.z;
    if (s == 3) r = v.w;
    return r;
}

// order-preserving float -> uint key (no NaNs in input)
__device__ __forceinline__ unsigned fkey(float f) {
    unsigned u = __float_as_uint(f);
    return u ^ ((unsigned)((int)u >> 31) | 0x80000000u);
}

// per-lane best of 8 elements (first-occurrence within lane: increasing cols)
__device__ __forceinline__ void lane_best(float4 p0, float4 p1, int c0, int c1,
                                          float& best, int& bidx) {
    best = p0.x; bidx = c0;
    if (p0.y > best) { best = p0.y; bidx = c0 + 1; }
    if (p0.z > best) { best = p0.z; bidx = c0 + 2; }
    if (p0.w > best) { best = p0.w; bidx = c0 + 3; }
    if (p1.x > best) { best = p1.x; bidx = c1;     }
    if (p1.y > best) { best = p1.y; bidx = c1 + 1; }
    if (p1.z > best) { best = p1.z; bidx = c1 + 2; }
    if (p1.w > best) { best = p1.w; bidx = c1 + 3; }
}

// warp argmax via redux.sync; owner = lowest matching lane (first occurrence)
__device__ __forceinline__ void warp_argmax(float best, int bidx, unsigned F,
                                            float& m, int& j) {
    const unsigned k = fkey(best);
    const unsigned w = __reduce_max_sync(F, k);
    const unsigned bal = __ballot_sync(F, k == w);
    const int owner = __ffs(bal) - 1;
    m = __shfl_sync(F, best, owner);
    j = __shfl_sync(F, bidx, owner);
}

__global__ void __launch_bounds__(TPB)
fused_kernel(const float* __restrict__ a,
             const float* __restrict__ b,
             const int*   __restrict__ negc,
             float* __restrict__ out,   // [0]=loss, [1..256]=num_max
             int out_n) {
    const int tid  = threadIdx.x;
    const int bid  = blockIdx.x;
    const int warp = tid >> 5;
    const int lane = tid & 31;
    const unsigned F = 0xffffffffu;

    __shared__ int   s_e;
    __shared__ int   s_j[8];      // per-warp own-row argmax
    __shared__ float s_sum[8];    // per-warp loss contribution

    if (tid == 0) s_e = *(volatile int*)&g_ep[bid] + 1;

    // ---- row assignment: warp w<4 -> a-row arow; w>=4 -> b-row arow ----
    const int arow = bid * 4 + (warp & 3);            // 0..4095
    const bool is_b = warp >= 4;
    const int grow = is_b ? (arow + B_CONST) : arow;  // global row 0..8191
    const float* rown = is_b ? (b + (size_t)arow * D_CONST)
                             : (a + (size_t)arow * D_CONST);

    // random negative column (e1 = arow, e2 = arow + B for both rows of pair)
    int c = negc[grow];
    c += (c >= arow) ? 1 : 0;
    c += (c >= arow + B_CONST) ? 1 : 0;
    const float* rrand = (c < B_CONST) ? (a + (size_t)c * D_CONST)
                                       : (b + (size_t)(c - B_CONST) * D_CONST);

    // ---- all 4 row loads front-batched (MLP=4/thread) ----
    const int c0 = lane * 4;
    const int c1 = 128 + lane * 4;
    float4 v0 = *reinterpret_cast<const float4*>(rown  + c0);
    float4 v1 = *reinterpret_cast<const float4*>(rown  + c1);
    float4 w0 = *reinterpret_cast<const float4*>(rrand + c0);
    float4 w1 = *reinterpret_cast<const float4*>(rrand + c1);

    // block 0: zero output (poisoned 0xAA), stamp flag
    if (bid == 0) {
        for (int i = tid; i < out_n; i += TPB) out[i] = 0.0f;
        __syncthreads();
        if (tid == 0) {
            __threadfence();
            *(volatile int*)&g_zflag = s_e;
        }
    }

    // ---- argmax of own row and of the random row ----
    float bl; int bi;
    float m0, mR;
    int   j0, jR;
    lane_best(v0, v1, c0, c1, bl, bi);  warp_argmax(bl, bi, F, m0, j0);
    lane_best(w0, w1, c0, c1, bl, bi);  warp_argmax(bl, bi, F, mR, jR);

    // negative: neg = m0 - own_row[jR]  (register shuffle extraction)
    const float g = __shfl_sync(F, (jR < 128) ? pick4(v0, jR & 3)
                                              : pick4(v1, jR & 3),
                                (jR >> 2) & 31);
    const float md = fmaxf(1.0f - (m0 - g), 0.0f);

    // exchange own-argmax with partner warp (w ^ 4 holds the paired row)
    if (lane == 0) s_j[warp] = j0;
    __syncthreads();
    const int jP = s_j[warp ^ 4];

    // positive: pos = m0 - own_row[jP]
    const float f = __shfl_sync(F, (jP < 128) ? pick4(v0, jP & 3)
                                              : pick4(v1, jP & 3),
                                (jP >> 2) & 31);
    const float contrib = (m0 - f) + md * md;

    if (lane == 0) s_sum[warp] = contrib;
    __syncthreads();

    // ---- warp 0 finishes the block ----
    if (warp == 0) {
        const int e = s_e;
        volatile int* zf = &g_zflag;
        while (*zf < e) { }                          // output guaranteed zeroed

        if (lane < 8)
            atomicAdd(&out[1 + s_j[lane]], 1.0f);    // hist (8 rows)

        float v = (lane < 8) ? s_sum[lane] : 0.0f;
        #pragma unroll
        for (int off = 4; off; off >>= 1)
            v += __shfl_down_sync(F, v, off);
        if (lane == 0) {
            atomicAdd(&out[0], 0.5f * v);            // sum(...)/2
            *(volatile int*)&g_ep[bid] = e;          // advance launch counter
        }
    }
}

extern "C" void kernel_launch(void* const* d_in, const int* in_sizes, int n_in,
                              void* d_out, int out_size) {
    const float* a    = (const float*)d_in[0];   // out_a [4096,256] f32
    const float* b    = (const float*)d_in[1];   // out_b [4096,256] f32
    const int*   negc = (const int*)  d_in[2];   // neg_choice [8192] i32
    float* out = (float*)d_out;

    fused_kernel<<<GRID, TPB>>>(a, b, negc, out, out_size);
}

// round 12
// speedup vs baseline: 1.0393x; 1.0393x over previous
#include <cuda_runtime.h>
#include <math_constants.h>

#define B_CONST 4096
#define D_CONST 256
#define N_CONST 8192
#define GRID    256
#define TPB     512      // 16 warps/block ; 256*16 = 4096 pairs

// scratch (device globals — allocation forbidden; zero-initialized at load)
__device__ int g_ep[GRID];   // per-block launch counter
__device__ int g_zflag = 0;  // epoch stamp: "output zeroed by block 0"

__device__ __forceinline__ float pick4(float4 v, int s) {
    float r = v.x;
    if (s == 1) r = v.y;
    if (s == 2) r = v.z;
    if (s == 3) r = v.w;
    return r;
}

// order-preserving float -> uint key (no NaNs in input)
__device__ __forceinline__ unsigned fkey(float f) {
    unsigned u = __float_as_uint(f);
    return u ^ ((unsigned)((int)u >> 31) | 0x80000000u);
}

// per-lane best of 8 elements (increasing cols -> first occurrence in lane)
__device__ __forceinline__ void lane_best(float4 p0, float4 p1, int c0, int c1,
                                          float& best, int& bidx) {
    best = p0.x; bidx = c0;
    if (p0.y > best) { best = p0.y; bidx = c0 + 1; }
    if (p0.z > best) { best = p0.z; bidx = c0 + 2; }
    if (p0.w > best) { best = p0.w; bidx = c0 + 3; }
    if (p1.x > best) { best = p1.x; bidx = c1;     }
    if (p1.y > best) { best = p1.y; bidx = c1 + 1; }
    if (p1.z > best) { best = p1.z; bidx = c1 + 2; }
    if (p1.w > best) { best = p1.w; bidx = c1 + 3; }
}

// warp argmax via redux.sync; owner = lowest matching lane (first occurrence)
__device__ __forceinline__ void warp_argmax(float best, int bidx, unsigned F,
                                            float& m, int& j) {
    const unsigned k = fkey(best);
    const unsigned w = __reduce_max_sync(F, k);
    const unsigned bal = __ballot_sync(F, k == w);
    const int owner = __ffs(bal) - 1;
    m = __shfl_sync(F, best, owner);
    j = __shfl_sync(F, bidx, owner);
}

__global__ void __launch_bounds__(TPB)
fused_kernel(const float* __restrict__ a,
             const float* __restrict__ b,
             const int*   __restrict__ negc,
             float* __restrict__ out,   // [0]=loss, [1..256]=num_max
             int out_n) {
    const int tid  = threadIdx.x;
    const int bid  = blockIdx.x;
    const int warp = tid >> 5;
    const int lane = tid & 31;
    const unsigned F = 0xffffffffu;

    __shared__ float s_sum[16];

    // every warp reads its block's epoch itself (replicated 4B L2 load);
    // g_ep[bid] is only WRITTEN after the final __syncthreads -> safe order.
    const int e = *(volatile int*)&g_ep[bid] + 1;

    // ---- indices & all 8 row loads issued up front (MLP=8/thread) ----
    const int arow = bid * 16 + warp;                 // pair index 0..4095
    const float* r0 = a + (size_t)arow * D_CONST;     // row i   = arow
    const float* r1 = b + (size_t)arow * D_CONST;     // row i+B

    int cA = negc[arow];
    cA += (cA >= arow) ? 1 : 0;
    cA += (cA >= arow + B_CONST) ? 1 : 0;
    int cB = negc[arow + B_CONST];
    cB += (cB >= arow) ? 1 : 0;
    cB += (cB >= arow + B_CONST) ? 1 : 0;
    const float* rA = (cA < B_CONST) ? (a + (size_t)cA * D_CONST)
                                     : (b + (size_t)(cA - B_CONST) * D_CONST);
    const float* rB = (cB < B_CONST) ? (a + (size_t)cB * D_CONST)
                                     : (b + (size_t)(cB - B_CONST) * D_CONST);

    const int c0 = lane * 4;
    const int c1 = 128 + lane * 4;
    float4 v00 = *reinterpret_cast<const float4*>(r0 + c0);
    float4 v01 = *reinterpret_cast<const float4*>(r0 + c1);
    float4 v10 = *reinterpret_cast<const float4*>(r1 + c0);
    float4 v11 = *reinterpret_cast<const float4*>(r1 + c1);
    float4 w00 = *reinterpret_cast<const float4*>(rA + c0);
    float4 w01 = *reinterpret_cast<const float4*>(rA + c1);
    float4 w10 = *reinterpret_cast<const float4*>(rB + c0);
    float4 w11 = *reinterpret_cast<const float4*>(rB + c1);

    // block 0: zero output (poisoned 0xAA), stamp flag
    if (bid == 0) {
        for (int i = tid; i < out_n; i += TPB) out[i] = 0.0f;
        __syncthreads();
        if (tid == 0) {
            __threadfence();
            *(volatile int*)&g_zflag = e;
        }
    }

    // ---- 4 warp argmaxes via redux ----
    float bl; int bi;
    float m0, m1, mA, mB;
    int   j0, j1, jA, jB;
    lane_best(v00, v01, c0, c1, bl, bi);  warp_argmax(bl, bi, F, m0, j0);
    lane_best(v10, v11, c0, c1, bl, bi);  warp_argmax(bl, bi, F, m1, j1);
    lane_best(w00, w01, c0, c1, bl, bi);  warp_argmax(bl, bi, F, mA, jA);
    lane_best(w10, w11, c0, c1, bl, bi);  warp_argmax(bl, bi, F, mB, jB);

    // positives: pos_a = m0 - row_a[j1] ; pos_b = m1 - row_b[j0]
    float fa = __shfl_sync(F, (j1 < 128) ? pick4(v00, j1 & 3) : pick4(v01, j1 & 3),
                           (j1 >> 2) & 31);
    float fb = __shfl_sync(F, (j0 < 128) ? pick4(v10, j0 & 3) : pick4(v11, j0 & 3),
                           (j0 >> 2) & 31);
    // negatives: neg_a = m0 - row_a[jA] ; neg_b = m1 - row_b[jB]
    float ga = __shfl_sync(F, (jA < 128) ? pick4(v00, jA & 3) : pick4(v01, jA & 3),
                           (jA >> 2) & 31);
    float gb = __shfl_sync(F, (jB < 128) ? pick4(v10, jB & 3) : pick4(v11, jB & 3),
                           (jB >> 2) & 31);

    const float mdA = fmaxf(1.0f - (m0 - ga), 0.0f);
    const float mdB = fmaxf(1.0f - (m1 - gb), 0.0f);
    const float contrib = (m0 - fa) + (m1 - fb) + mdA * mdA + mdB * mdB;

    // ---- per-warp tail: hist atomics fire-and-forget after zflag gate ----
    if (lane == 0) {
        volatile int* zf = &g_zflag;
        while (*zf < e) { }                    // output zeroed (stamped early)
        atomicAdd(&out[1 + j0], 1.0f);         // num_max histogram
        atomicAdd(&out[1 + j1], 1.0f);
        s_sum[warp] = contrib;
    }
    __syncthreads();

    // ---- warp 0: single loss atomic per block ----
    if (warp == 0) {
        float v = (lane < 16) ? s_sum[lane] : 0.0f;
        #pragma unroll
        for (int off = 8; off; off >>= 1)
            v += __shfl_down_sync(F, v, off);
        if (lane == 0) {
            atomicAdd(&out[0], 0.5f * v);      // sum(...)/2
            *(volatile int*)&g_ep[bid] = e;    // advance launch counter
        }
    }
}

extern "C" void kernel_launch(void* const* d_in, const int* in_sizes, int n_in,
                              void* d_out, int out_size) {
    const float* a    = (const float*)d_in[0];   // out_a [4096,256] f32
    const float* b    = (const float*)d_in[1];   // out_b [4096,256] f32
    const int*   negc = (const int*)  d_in[2];   // neg_choice [8192] i32
    float* out = (float*)d_out;

    fused_kernel<<<GRID, TPB>>>(a, b, negc, out, out_size);
}